// round 1
// baseline (speedup 1.0000x reference)
#include <cuda_runtime.h>
#include <math.h>

#define Nn 2048
#define Cc 1024
#define Hh 8
#define Dd 128
#define SCALE_F 25.0f

// ---------------- scratch (static device globals; no allocs) ----------------
__device__ __align__(128) float g_qkv_cls[Nn * 3 * Cc];     // [N,3,H,d]
__device__ __align__(128) float g_qkv_reg[Nn * 3 * Cc];
__device__ __align__(128) float g_qn[2 * Hh * Nn * Dd];     // normalized q, [set][H][N][d]
__device__ __align__(128) float g_kn[2 * Hh * Nn * Dd];     // normalized*SCALE*score k
__device__ __align__(128) float g_v[Hh * Nn * Dd];          // raw v_cls, [H][N][d]
__device__ __align__(128) float g_vn[Nn * Cc];              // per-head-normalized v, [N, H*d]
__device__ __align__(128) float g_S0[Hh * Nn * Nn];         // cls scores -> attn probs
__device__ __align__(128) float g_S1[Hh * Nn * Nn];         // reg scores
__device__ __align__(128) float g_simraw[Nn * Nn];          // sum_h vn.vn
__device__ __align__(128) float g_attnsum[Nn * Nn];         // sum_h attn
__device__ __align__(128) float g_x[Nn * 2 * Cc];           // trans_cls = [x | x_ori]
__device__ __align__(128) float g_sim2[Nn * Nn];            // sim_round2
__device__ __align__(128) float g_ave[Nn * 4 * Cc];         // [soft_sim | feat]

// ---------------- reductions ----------------
__device__ __forceinline__ float warpMax(float v) {
#pragma unroll
    for (int o = 16; o; o >>= 1) v = fmaxf(v, __shfl_xor_sync(0xffffffffu, v, o));
    return v;
}
__device__ __forceinline__ float warpSum(float v) {
#pragma unroll
    for (int o = 16; o; o >>= 1) v += __shfl_xor_sync(0xffffffffu, v, o);
    return v;
}
// blockDim.x == 256 (8 warps)
__device__ float blockMax(float v, float* s) {
    int w = threadIdx.x >> 5, l = threadIdx.x & 31;
    v = warpMax(v);
    if (l == 0) s[w] = v;
    __syncthreads();
    float r = (l < 8) ? s[l] : -3.0e38f;
    r = warpMax(r);
    r = __shfl_sync(0xffffffffu, r, 0);
    __syncthreads();
    return r;
}
__device__ float blockSum(float v, float* s) {
    int w = threadIdx.x >> 5, l = threadIdx.x & 31;
    v = warpSum(v);
    if (l == 0) s[w] = v;
    __syncthreads();
    float r = (l < 8) ? s[l] : 0.0f;
    r = warpSum(r);
    r = __shfl_sync(0xffffffffu, r, 0);
    __syncthreads();
    return r;
}

// ---------------- SGEMM: C = A @ op(B) (+bias) ----------------
// TRANSB=true : B is [N,K] row-major (ldb)  -> C = A*B^T
// TRANSB=false: B is [K,N] row-major (ldb)  -> C = A*B
// Requires M%128==0, N%128==0, K%8==0, lda/ldb%4==0, 16B-aligned bases.
template <bool TRANSB>
__global__ void __launch_bounds__(256) gemm_f32(
    const float* __restrict__ A, const float* __restrict__ B, float* __restrict__ C,
    const float* __restrict__ bias,
    int M, int N, int K, int lda, int ldb, int ldc,
    long long sA, long long sB, long long sC)
{
    __shared__ __align__(16) float As[2][8][128];
    __shared__ __align__(16) float Bs[2][8][128];

    A += (long long)blockIdx.z * sA;
    B += (long long)blockIdx.z * sB;
    C += (long long)blockIdx.z * sC;

    const int m0 = blockIdx.y * 128;
    const int n0 = blockIdx.x * 128;
    const int t  = threadIdx.x;
    const int tx = t & 15, ty = t >> 4;

    // A-tile loader (also B when TRANSB): 128 rows x 8 k, float4 along k
    const int arow = t >> 1;
    const int acol = (t & 1) * 4;
    // B-tile loader for NN: 8 k-rows x 128 cols, float4 along n
    const int bk = t >> 5;
    const int bn = (t & 31) * 4;

    float acc[8][8];
#pragma unroll
    for (int i = 0; i < 8; i++)
#pragma unroll
        for (int j = 0; j < 8; j++) acc[i][j] = 0.0f;

    const int ntiles = K >> 3;

    // prologue: tile 0
    float4 a4 = *(const float4*)(A + (long long)(m0 + arow) * lda + acol);
    float4 b4;
    if (TRANSB) b4 = *(const float4*)(B + (long long)(n0 + arow) * ldb + acol);
    else        b4 = *(const float4*)(B + (long long)bk * ldb + n0 + bn);

    As[0][acol + 0][arow] = a4.x;
    As[0][acol + 1][arow] = a4.y;
    As[0][acol + 2][arow] = a4.z;
    As[0][acol + 3][arow] = a4.w;
    if (TRANSB) {
        Bs[0][acol + 0][arow] = b4.x;
        Bs[0][acol + 1][arow] = b4.y;
        Bs[0][acol + 2][arow] = b4.z;
        Bs[0][acol + 3][arow] = b4.w;
    } else {
        *(float4*)&Bs[0][bk][bn] = b4;
    }
    __syncthreads();

    int buf = 0;
    for (int tile = 0; tile < ntiles; ++tile) {
        float4 a4n, b4n;
        const bool more = (tile + 1 < ntiles);
        if (more) {
            const int k0 = (tile + 1) << 3;
            a4n = *(const float4*)(A + (long long)(m0 + arow) * lda + k0 + acol);
            if (TRANSB) b4n = *(const float4*)(B + (long long)(n0 + arow) * ldb + k0 + acol);
            else        b4n = *(const float4*)(B + (long long)(k0 + bk) * ldb + n0 + bn);
        }

#pragma unroll
        for (int kk = 0; kk < 8; kk++) {
            float ar[8], br[8];
            *(float4*)&ar[0] = *(const float4*)&As[buf][kk][ty * 8];
            *(float4*)&ar[4] = *(const float4*)&As[buf][kk][ty * 8 + 4];
            *(float4*)&br[0] = *(const float4*)&Bs[buf][kk][tx * 8];
            *(float4*)&br[4] = *(const float4*)&Bs[buf][kk][tx * 8 + 4];
#pragma unroll
            for (int i = 0; i < 8; i++)
#pragma unroll
                for (int j = 0; j < 8; j++) acc[i][j] = fmaf(ar[i], br[j], acc[i][j]);
        }

        if (more) {
            buf ^= 1;
            As[buf][acol + 0][arow] = a4n.x;
            As[buf][acol + 1][arow] = a4n.y;
            As[buf][acol + 2][arow] = a4n.z;
            As[buf][acol + 3][arow] = a4n.w;
            if (TRANSB) {
                Bs[buf][acol + 0][arow] = b4n.x;
                Bs[buf][acol + 1][arow] = b4n.y;
                Bs[buf][acol + 2][arow] = b4n.z;
                Bs[buf][acol + 3][arow] = b4n.w;
            } else {
                *(float4*)&Bs[buf][bk][bn] = b4n;
            }
            __syncthreads();
        }
    }

    // epilogue (float4 stores)
#pragma unroll
    for (int i = 0; i < 8; i++) {
        const long long row = (long long)(m0 + ty * 8 + i) * ldc;
#pragma unroll
        for (int jg = 0; jg < 2; jg++) {
            const int col = n0 + tx * 8 + jg * 4;
            float4 o;
            o.x = acc[i][jg * 4 + 0];
            o.y = acc[i][jg * 4 + 1];
            o.z = acc[i][jg * 4 + 2];
            o.w = acc[i][jg * 4 + 3];
            if (bias) {
                o.x += bias[col + 0];
                o.y += bias[col + 1];
                o.z += bias[col + 2];
                o.w += bias[col + 3];
            }
            *(float4*)(C + row + col) = o;
        }
    }
}

// ---------------- split + normalize + fold column scales into K ----------------
// grid (N, H), block 128
__global__ void split_normalize(const float* __restrict__ cls_score,
                                const float* __restrict__ fg_score)
{
    const int n = blockIdx.x, h = blockIdx.y, j = threadIdx.x;
    const float* bc = g_qkv_cls + (size_t)n * 3 * Cc + h * Dd;
    const float* br = g_qkv_reg + (size_t)n * 3 * Cc + h * Dd;

    float qc = bc[0 * Cc + j], kc = bc[1 * Cc + j], vv = bc[2 * Cc + j];
    float qr = br[0 * Cc + j], kr = br[1 * Cc + j];

    float s[5] = {qc * qc, kc * kc, vv * vv, qr * qr, kr * kr};
    __shared__ float red[5][4];
    const int lane = j & 31, warp = j >> 5;
#pragma unroll
    for (int i = 0; i < 5; i++) {
        float v = warpSum(s[i]);
        if (lane == 0) red[i][warp] = v;
    }
    __syncthreads();
    float inv[5];
#pragma unroll
    for (int i = 0; i < 5; i++)
        inv[i] = 1.0f / sqrtf(red[i][0] + red[i][1] + red[i][2] + red[i][3]);

    const float sc_c = SCALE_F * cls_score[n];
    const float sc_f = SCALE_F * fg_score[n];
    const size_t off = ((size_t)h * Nn + n) * Dd + j;
    const size_t set1 = (size_t)Hh * Nn * Dd;

    g_qn[off]        = qc * inv[0];
    g_kn[off]        = kc * inv[1] * sc_c;
    g_qn[set1 + off] = qr * inv[3];
    g_kn[set1 + off] = kr * inv[4] * sc_f;
    g_v[off]         = vv;
    g_vn[(size_t)n * Cc + h * Dd + j] = vv * inv[2];
}

// ---------------- per-row dual softmax + head combine + head-sum ----------------
// grid (N), block 256
__global__ void __launch_bounds__(256) softmax_combine()
{
    const int n = blockIdx.x, t = threadIdx.x;
    __shared__ float sc[Nn];
    __shared__ float sr[Nn];
    __shared__ float acc[Nn];
    __shared__ float red[8];

    for (int m = t; m < Nn; m += 256) acc[m] = 0.0f;

    for (int h = 0; h < Hh; h++) {
        const size_t base = ((size_t)h * Nn + n) * Nn;
        float lmc = -3.0e38f, lmr = -3.0e38f;
        for (int m = t; m < Nn; m += 256) {
            float a = g_S0[base + m];
            float b = g_S1[base + m];
            sc[m] = a; sr[m] = b;
            lmc = fmaxf(lmc, a);
            lmr = fmaxf(lmr, b);
        }
        const float mc = blockMax(lmc, red);
        const float mr = blockMax(lmr, red);
        float lsc = 0.0f, lsr = 0.0f;
        for (int m = t; m < Nn; m += 256) {
            float ec = expf(sc[m] - mc);
            float er = expf(sr[m] - mr);
            sc[m] = ec; sr[m] = er;
            lsc += ec; lsr += er;
        }
        const float ic = 0.5f / blockSum(lsc, red);
        const float ir = 0.5f / blockSum(lsr, red);
        for (int m = t; m < Nn; m += 256) {
            float p = sc[m] * ic + sr[m] * ir;
            g_S0[base + m] = p;   // combined attn prob for this head
            acc[m] += p;
        }
        __syncthreads();
    }
    for (int m = t; m < Nn; m += 256) g_attnsum[(size_t)n * Nn + m] = acc[m];
}

// ---------------- mask + softmax round 2 + renormalize ----------------
// grid (N), block 256
__global__ void __launch_bounds__(256) mask_softmax2()
{
    const int n = blockIdx.x, t = threadIdx.x;
    __shared__ float buf[Nn];
    __shared__ float red[8];

    float lm = -3.0e38f;
    for (int m = t; m < Nn; m += 256) {
        float v = g_attnsum[(size_t)n * Nn + m] * 0.125f;   // /H (exact)
        buf[m] = v;
        lm = fmaxf(lm, v);
    }
    const float mx = blockMax(lm, red);
    float ls = 0.0f;
    for (int m = t; m < Nn; m += 256) {
        float e = expf(buf[m] - mx);
        buf[m] = e;
        ls += e;
    }
    const float inv = 1.0f / blockSum(ls, red);
    float lms = 0.0f;
    for (int m = t; m < Nn; m += 256) {
        float p = buf[m] * inv;
        // sim_raw = simraw/8 > 0.75  <=>  simraw > 6 (exact: /8 is a pow2 scale)
        float keep = (g_simraw[(size_t)n * Nn + m] > 6.0f) ? p : 0.0f;
        buf[m] = keep;
        lms += keep;
    }
    const float invm = 1.0f / blockSum(lms, red);
    for (int m = t; m < Nn; m += 256) g_sim2[(size_t)n * Nn + m] = buf[m] * invm;
}

// ---------------- x_ori copy: trans_cls[:,C:2C] = v slice of qkv_cls ----------------
__global__ void copy_xori()
{
    const int idx = blockIdx.x * 256 + threadIdx.x;  // 0 .. N*C-1
    const int n = idx >> 10;
    const int c = idx & 1023;
    g_x[(size_t)n * 2 * Cc + Cc + c] = g_qkv_cls[(size_t)n * 3 * Cc + 2 * Cc + c];
}

// ---------------- launch ----------------
extern "C" void kernel_launch(void* const* d_in, const int* in_sizes, int n_in,
                              void* d_out, int out_size)
{
    const float* x_cls     = (const float*)d_in[0];
    const float* x_reg     = (const float*)d_in[1];
    const float* cls_score = (const float*)d_in[2];
    const float* fg_score  = (const float*)d_in[3];
    const float* W_qkv_cls = (const float*)d_in[4];
    const float* W_qkv_reg = (const float*)d_in[5];
    const float* W1        = (const float*)d_in[6];
    const float* b1        = (const float*)d_in[7];
    const float* W2        = (const float*)d_in[8];
    const float* b2        = (const float*)d_in[9];
    float* out = (float*)d_out;

    float *qkvc, *qkvr, *qn, *kn, *vv, *vn, *S0, *S1, *simraw, *xbuf, *sim2, *ave;
    cudaGetSymbolAddress((void**)&qkvc, g_qkv_cls);
    cudaGetSymbolAddress((void**)&qkvr, g_qkv_reg);
    cudaGetSymbolAddress((void**)&qn, g_qn);
    cudaGetSymbolAddress((void**)&kn, g_kn);
    cudaGetSymbolAddress((void**)&vv, g_v);
    cudaGetSymbolAddress((void**)&vn, g_vn);
    cudaGetSymbolAddress((void**)&S0, g_S0);
    cudaGetSymbolAddress((void**)&S1, g_S1);
    cudaGetSymbolAddress((void**)&simraw, g_simraw);
    cudaGetSymbolAddress((void**)&xbuf, g_x);
    cudaGetSymbolAddress((void**)&sim2, g_sim2);
    cudaGetSymbolAddress((void**)&ave, g_ave);

    const long long HND = (long long)Hh * Nn * Dd;
    const long long NN  = (long long)Nn * Nn;

    // 1,2: qkv projections
    gemm_f32<true><<<dim3(3 * Cc / 128, Nn / 128, 1), 256>>>(
        x_cls, W_qkv_cls, qkvc, nullptr, Nn, 3 * Cc, Cc, Cc, Cc, 3 * Cc, 0, 0, 0);
    gemm_f32<true><<<dim3(3 * Cc / 128, Nn / 128, 1), 256>>>(
        x_reg, W_qkv_reg, qkvr, nullptr, Nn, 3 * Cc, Cc, Cc, Cc, 3 * Cc, 0, 0, 0);

    // 3: split heads, normalize, fold SCALE*score into k
    split_normalize<<<dim3(Nn, Hh), 128>>>(cls_score, fg_score);

    // 4: batched score GEMMs (per head) + simraw GEMM
    gemm_f32<true><<<dim3(Nn / 128, Nn / 128, Hh), 256>>>(
        qn, kn, S0, nullptr, Nn, Nn, Dd, Dd, Dd, Nn,
        (long long)Nn * Dd, (long long)Nn * Dd, NN);
    gemm_f32<true><<<dim3(Nn / 128, Nn / 128, Hh), 256>>>(
        qn + HND, kn + HND, S1, nullptr, Nn, Nn, Dd, Dd, Dd, Nn,
        (long long)Nn * Dd, (long long)Nn * Dd, NN);
    gemm_f32<true><<<dim3(Nn / 128, Nn / 128, 1), 256>>>(
        vn, vn, simraw, nullptr, Nn, Nn, Cc, Cc, Cc, Nn, 0, 0, 0);

    // 5: dual softmax + combine heads (writes probs back into S0, head-sums to attnsum)
    softmax_combine<<<Nn, 256>>>();

    // 6: x = attn @ v (per head), columns h*d of trans_cls
    gemm_f32<false><<<dim3(1, Nn / 128, Hh), 256>>>(
        S0, vv, xbuf, nullptr, Nn, Dd, Nn, Nn, Dd, 2 * Cc,
        NN, (long long)Nn * Dd, (long long)Dd);

    // x_ori copy into trans_cls[:, C:2C]
    copy_xori<<<(Nn * Cc) / 256, 256>>>();

    // 7: feat = trans_cls @ W1^T + b1  -> ave[:, 2C:4C]
    gemm_f32<true><<<dim3(2 * Cc / 128, Nn / 128, 1), 256>>>(
        xbuf, W1, ave + 2 * Cc, b1, Nn, 2 * Cc, 2 * Cc, 2 * Cc, 2 * Cc, 4 * Cc, 0, 0, 0);

    // 8: sim_round2 (softmax + mask + renorm)
    mask_softmax2<<<Nn, 256>>>();

    // 9: soft_sim = sim_round2 @ feat -> ave[:, 0:2C]
    gemm_f32<false><<<dim3(2 * Cc / 128, Nn / 128, 1), 256>>>(
        sim2, ave + 2 * Cc, ave, nullptr, Nn, 2 * Cc, Nn, Nn, 4 * Cc, 4 * Cc, 0, 0, 0);

    // 10: out = ave @ W2^T + b2
    gemm_f32<true><<<dim3(Cc / 128, Nn / 128, 1), 256>>>(
        ave, W2, out, b2, Nn, Cc, 4 * Cc, 4 * Cc, 4 * Cc, Cc, 0, 0, 0);
}